// round 1
// baseline (speedup 1.0000x reference)
#include <cuda_runtime.h>

#define NN 100000          // nodes
#define DIM 64             // embed dim
#define NE 1600000         // edges
#define NL 100000          // label edges
#define NLAYERS 3
__device__ __constant__ float kAlpha = 1.0f / (NLAYERS + 1);   // 0.25

// ---------------- scratch (device globals; no allocation allowed) -------------
__device__ float g_deg[NN];          // degree, then deg^-1/2 in place
__device__ float g_norm[NE];         // per-edge norm
__device__ float g_A[NN * DIM];      // ping
__device__ float g_B[NN * DIM];      // pong
__device__ float g_out[NN * DIM];    // LightGCN accumulated embedding
__device__ float g_pred[NL];         // MLP predictions

// ---------------- small utility kernels --------------------------------------
__global__ void zero_kernel(float* __restrict__ p, int n) {
    int i = blockIdx.x * blockDim.x + threadIdx.x;
    if (i < n) p[i] = 0.0f;
}

__global__ void deg_kernel(const int* __restrict__ dst) {
    int e = blockIdx.x * blockDim.x + threadIdx.x;
    if (e < NE) atomicAdd(&g_deg[dst[e]], 1.0f);
}

__global__ void dis_kernel() {
    int i = blockIdx.x * blockDim.x + threadIdx.x;
    if (i < NN) {
        float d = g_deg[i];
        g_deg[i] = (d > 0.0f) ? rsqrtf(fmaxf(d, 1e-12f)) : 0.0f;
    }
}

__global__ void norm_kernel(const int* __restrict__ src, const int* __restrict__ dst) {
    int e = blockIdx.x * blockDim.x + threadIdx.x;
    if (e < NE) g_norm[e] = g_deg[src[e]] * g_deg[dst[e]];
}

__global__ void init_out_kernel(const float* __restrict__ emb) {
    int i = blockIdx.x * blockDim.x + threadIdx.x;
    if (i < NN * DIM) g_out[i] = emb[i] * kAlpha;
}

__global__ void accum_kernel(const float* __restrict__ x) {
    int i = blockIdx.x * blockDim.x + threadIdx.x;
    if (i < NN * DIM) g_out[i] += x[i] * kAlpha;
}

// ---------------- propagation: x_out[dst] += norm * x_in[src] ----------------
// 16 lanes per edge; each lane handles one float4 (16B). Gather is 256B
// contiguous per edge; scatter is 4 scalar float atomics per lane.
__global__ void prop_kernel(const float* __restrict__ xin,
                            float* __restrict__ xout,
                            const int* __restrict__ src,
                            const int* __restrict__ dst) {
    long long idx = (long long)blockIdx.x * blockDim.x + threadIdx.x;
    int e = (int)(idx >> 4);
    if (e >= NE) return;
    int lane = (int)(idx & 15);

    int s = __ldg(src + e);
    int d = __ldg(dst + e);
    float nrm = __ldg(g_norm + e);

    const float4 v = *reinterpret_cast<const float4*>(xin + (long long)s * DIM + lane * 4);
    float* o = xout + (long long)d * DIM + lane * 4;
    atomicAdd(o + 0, v.x * nrm);
    atomicAdd(o + 1, v.y * nrm);
    atomicAdd(o + 2, v.z * nrm);
    atomicAdd(o + 3, v.w * nrm);
}

// ---------------- MLP scorer: one block (64 threads) per label edge ----------
// h = relu([out[s]; out[d]] @ W1 + b1);  pred = h @ W2 + b2
__global__ void mlp_kernel(const int* __restrict__ lsrc,
                           const int* __restrict__ ldst,
                           const float* __restrict__ W1,   // [128,64] row-major
                           const float* __restrict__ b1,   // [64]
                           const float* __restrict__ W2,   // [64]
                           const float* __restrict__ b2) { // [1]
    __shared__ float sh_in[2 * DIM];
    __shared__ float sh_h[DIM];
    int l = blockIdx.x;
    int t = threadIdx.x;   // 0..63

    int s = __ldg(lsrc + l);
    int d = __ldg(ldst + l);
    sh_in[t]       = g_out[(long long)s * DIM + t];
    sh_in[DIM + t] = g_out[(long long)d * DIM + t];
    __syncthreads();

    float acc = __ldg(b1 + t);
#pragma unroll 8
    for (int i = 0; i < 2 * DIM; i++)
        acc = fmaf(sh_in[i], __ldg(W1 + i * DIM + t), acc);
    acc = fmaxf(acc, 0.0f);
    sh_h[t] = acc * __ldg(W2 + t);
    __syncthreads();

    if (t < 32) {
        float v = sh_h[t] + sh_h[t + 32];
#pragma unroll
        for (int off = 16; off > 0; off >>= 1)
            v += __shfl_down_sync(0xffffffffu, v, off);
        if (t == 0) g_pred[l] = v + __ldg(b2);
    }
}

// ---------------- output: pred copy + MSE loss -------------------------------
__global__ void pred_copy_kernel(float* __restrict__ out, int n) {
    int i = blockIdx.x * blockDim.x + threadIdx.x;
    if (i < n) out[i] = g_pred[i];
}

__global__ void zero_one_kernel(float* p) {
    if (threadIdx.x == 0 && blockIdx.x == 0) *p = 0.0f;
}

__global__ void loss_kernel(const float* __restrict__ label, float* __restrict__ out_loss) {
    __shared__ float sh[256];
    float acc = 0.0f;
    for (int i = blockIdx.x * blockDim.x + threadIdx.x; i < NL; i += gridDim.x * blockDim.x) {
        float diff = g_pred[i] - label[i];
        acc += diff * diff;
    }
    sh[threadIdx.x] = acc;
    __syncthreads();
    for (int stride = 128; stride > 0; stride >>= 1) {
        if (threadIdx.x < stride) sh[threadIdx.x] += sh[threadIdx.x + stride];
        __syncthreads();
    }
    if (threadIdx.x == 0) atomicAdd(out_loss, sh[0] * (1.0f / NL));
}

// ---------------- host launcher ----------------------------------------------
extern "C" void kernel_launch(void* const* d_in, const int* in_sizes, int n_in,
                              void* d_out, int out_size) {
    const int*   ei   = (const int*)d_in[0];       // [2, NE]
    const int*   eli  = (const int*)d_in[1];       // [2, NL]
    const float* elab = (const float*)d_in[2];     // [NL]
    const float* emb  = (const float*)d_in[3];     // [NN, 64]
    const float* W1   = (const float*)d_in[4];     // [128, 64]
    const float* b1   = (const float*)d_in[5];     // [64]
    const float* W2   = (const float*)d_in[6];     // [64, 1]
    const float* b2   = (const float*)d_in[7];     // [1]
    float* out = (float*)d_out;

    const int* src = ei;
    const int* dst = ei + NE;
    const int* lsrc = eli;
    const int* ldst = eli + NL;

    float *pDeg, *pA, *pB;
    cudaGetSymbolAddress((void**)&pDeg, g_deg);
    cudaGetSymbolAddress((void**)&pA,   g_A);
    cudaGetSymbolAddress((void**)&pB,   g_B);

    const int T = 256;
    const int nND  = NN * DIM;                     // 6.4M
    const int gND  = (nND + T - 1) / T;
    const int gE   = (NE + T - 1) / T;
    const int gN   = (NN + T - 1) / T;
    const int gP   = (NE * 16 + T - 1) / T;        // prop grid (16 lanes/edge)

    // ---- degree & norm ----
    zero_kernel<<<gN, T>>>(pDeg, NN);
    deg_kernel<<<gE, T>>>(dst);
    dis_kernel<<<gN, T>>>();
    norm_kernel<<<gE, T>>>(src, dst);

    // ---- LightGCN propagation: out = sum_l alpha * x^(l) ----
    init_out_kernel<<<gND, T>>>(emb);

    zero_kernel<<<gND, T>>>(pA, nND);
    prop_kernel<<<gP, T>>>(emb, pA, src, dst);     // layer 1: emb -> A
    accum_kernel<<<gND, T>>>(pA);

    zero_kernel<<<gND, T>>>(pB, nND);
    prop_kernel<<<gP, T>>>(pA, pB, src, dst);      // layer 2: A -> B
    accum_kernel<<<gND, T>>>(pB);

    zero_kernel<<<gND, T>>>(pA, nND);
    prop_kernel<<<gP, T>>>(pB, pA, src, dst);      // layer 3: B -> A
    accum_kernel<<<gND, T>>>(pA);

    // ---- scorer MLP ----
    mlp_kernel<<<NL, DIM>>>(lsrc, ldst, W1, b1, W2, b2);

    // ---- outputs: pred first, then loss in the trailing slot (if present) ----
    int npred = out_size < NL ? out_size : NL;
    if (npred > 0)
        pred_copy_kernel<<<(npred + T - 1) / T, T>>>(out, npred);
    if (out_size != NL) {
        float* lossp = out + (out_size - 1);
        zero_one_kernel<<<1, 32>>>(lossp);
        loss_kernel<<<132, 256>>>(elab, lossp);
    }
}

// round 2
// speedup vs baseline: 1.7586x; 1.7586x over previous
#include <cuda_runtime.h>

#define NN 100000          // nodes
#define DIM 64             // embed dim
#define NE 1600000         // edges
#define NL 100000          // label edges
#define NLAYERS 3
#define ALPHA 0.25f        // 1/(NLAYERS+1)

// ---------------- scratch (device globals; no allocation allowed) -------------
__device__ float g_deg[NN];          // degree, then deg^-1/2 in place
__device__ float g_norm[NE];         // per-edge norm
__device__ float g_A[NN * DIM];      // ping
__device__ float g_B[NN * DIM];      // pong
__device__ float g_out[NN * DIM];    // LightGCN accumulated embedding
__device__ float g_pred[NL];         // MLP predictions

// vectorized 16B float reduction (sm_90+)
__device__ __forceinline__ void red_add_v4(float* addr, float x, float y, float z, float w) {
    asm volatile("red.global.add.v4.f32 [%0], {%1, %2, %3, %4};"
                 :: "l"(addr), "f"(x), "f"(y), "f"(z), "f"(w) : "memory");
}

// ---------------- small utility kernels --------------------------------------
__global__ void zero_kernel(float* __restrict__ p, int n) {
    int i = blockIdx.x * blockDim.x + threadIdx.x;
    if (i < n) p[i] = 0.0f;
}

__global__ void deg_kernel(const int* __restrict__ dst) {
    int e = blockIdx.x * blockDim.x + threadIdx.x;
    if (e < NE) atomicAdd(&g_deg[dst[e]], 1.0f);
}

__global__ void dis_kernel() {
    int i = blockIdx.x * blockDim.x + threadIdx.x;
    if (i < NN) {
        float d = g_deg[i];
        g_deg[i] = (d > 0.0f) ? rsqrtf(fmaxf(d, 1e-12f)) : 0.0f;
    }
}

__global__ void norm_kernel(const int* __restrict__ src, const int* __restrict__ dst) {
    int e = blockIdx.x * blockDim.x + threadIdx.x;
    if (e < NE) g_norm[e] = g_deg[src[e]] * g_deg[dst[e]];
}

// g_out = emb * alpha; A = 0   (fused)
__global__ void init_out_zero_kernel(const float* __restrict__ emb, float* __restrict__ A) {
    int i = blockIdx.x * blockDim.x + threadIdx.x;
    if (i < NN * DIM) {
        g_out[i] = emb[i] * ALPHA;
        A[i] = 0.0f;
    }
}

// g_out += alpha * x; next = 0  (fused)
__global__ void accum_zero_kernel(const float* __restrict__ x, float* __restrict__ next) {
    int i = blockIdx.x * blockDim.x + threadIdx.x;
    if (i < NN * DIM) {
        g_out[i] += x[i] * ALPHA;
        next[i] = 0.0f;
    }
}

// g_out += alpha * x   (last layer)
__global__ void accum_kernel(const float* __restrict__ x) {
    int i = blockIdx.x * blockDim.x + threadIdx.x;
    if (i < NN * DIM) g_out[i] += x[i] * ALPHA;
}

// ---------------- propagation: x_out[dst] += norm * x_in[src] ----------------
// 16 lanes per edge; each lane handles one float4 (16B). Gather is 256B
// contiguous per edge; scatter is ONE red.global.add.v4.f32 per lane.
__global__ void __launch_bounds__(256) prop_kernel(const float* __restrict__ xin,
                            float* __restrict__ xout,
                            const int* __restrict__ src,
                            const int* __restrict__ dst) {
    long long idx = (long long)blockIdx.x * blockDim.x + threadIdx.x;
    int e = (int)(idx >> 4);
    if (e >= NE) return;
    int lane = (int)(idx & 15);

    int s = __ldg(src + e);
    int d = __ldg(dst + e);
    float nrm = __ldg(g_norm + e);

    const float4 v = *reinterpret_cast<const float4*>(xin + (long long)s * DIM + lane * 4);
    float* o = xout + (long long)d * DIM + lane * 4;
    red_add_v4(o, v.x * nrm, v.y * nrm, v.z * nrm, v.w * nrm);
}

// ---------------- MLP scorer: one block (64 threads) per label edge ----------
__global__ void mlp_kernel(const int* __restrict__ lsrc,
                           const int* __restrict__ ldst,
                           const float* __restrict__ W1,   // [128,64] row-major
                           const float* __restrict__ b1,   // [64]
                           const float* __restrict__ W2,   // [64]
                           const float* __restrict__ b2) { // [1]
    __shared__ float sh_in[2 * DIM];
    __shared__ float sh_h[DIM];
    int l = blockIdx.x;
    int t = threadIdx.x;   // 0..63

    int s = __ldg(lsrc + l);
    int d = __ldg(ldst + l);
    sh_in[t]       = g_out[(long long)s * DIM + t];
    sh_in[DIM + t] = g_out[(long long)d * DIM + t];
    __syncthreads();

    float acc = __ldg(b1 + t);
#pragma unroll 8
    for (int i = 0; i < 2 * DIM; i++)
        acc = fmaf(sh_in[i], __ldg(W1 + i * DIM + t), acc);
    acc = fmaxf(acc, 0.0f);
    sh_h[t] = acc * __ldg(W2 + t);
    __syncthreads();

    if (t < 32) {
        float v = sh_h[t] + sh_h[t + 32];
#pragma unroll
        for (int off = 16; off > 0; off >>= 1)
            v += __shfl_down_sync(0xffffffffu, v, off);
        if (t == 0) g_pred[l] = v + __ldg(b2);
    }
}

// ---------------- output: pred copy + MSE loss -------------------------------
__global__ void pred_copy_kernel(float* __restrict__ out, int n) {
    int i = blockIdx.x * blockDim.x + threadIdx.x;
    if (i < n) out[i] = g_pred[i];
}

__global__ void zero_one_kernel(float* p) {
    if (threadIdx.x == 0 && blockIdx.x == 0) *p = 0.0f;
}

__global__ void loss_kernel(const float* __restrict__ label, float* __restrict__ out_loss) {
    __shared__ float sh[256];
    float acc = 0.0f;
    for (int i = blockIdx.x * blockDim.x + threadIdx.x; i < NL; i += gridDim.x * blockDim.x) {
        float diff = g_pred[i] - label[i];
        acc += diff * diff;
    }
    sh[threadIdx.x] = acc;
    __syncthreads();
    for (int stride = 128; stride > 0; stride >>= 1) {
        if (threadIdx.x < stride) sh[threadIdx.x] += sh[threadIdx.x + stride];
        __syncthreads();
    }
    if (threadIdx.x == 0) atomicAdd(out_loss, sh[0] * (1.0f / NL));
}

// ---------------- host launcher ----------------------------------------------
extern "C" void kernel_launch(void* const* d_in, const int* in_sizes, int n_in,
                              void* d_out, int out_size) {
    const int*   ei   = (const int*)d_in[0];       // [2, NE]
    const int*   eli  = (const int*)d_in[1];       // [2, NL]
    const float* elab = (const float*)d_in[2];     // [NL]
    const float* emb  = (const float*)d_in[3];     // [NN, 64]
    const float* W1   = (const float*)d_in[4];     // [128, 64]
    const float* b1   = (const float*)d_in[5];     // [64]
    const float* W2   = (const float*)d_in[6];     // [64, 1]
    const float* b2   = (const float*)d_in[7];     // [1]
    float* out = (float*)d_out;

    const int* src = ei;
    const int* dst = ei + NE;
    const int* lsrc = eli;
    const int* ldst = eli + NL;

    float *pDeg, *pA, *pB;
    cudaGetSymbolAddress((void**)&pDeg, g_deg);
    cudaGetSymbolAddress((void**)&pA,   g_A);
    cudaGetSymbolAddress((void**)&pB,   g_B);

    const int T = 256;
    const int nND  = NN * DIM;                     // 6.4M
    const int gND  = (nND + T - 1) / T;
    const int gE   = (NE + T - 1) / T;
    const int gN   = (NN + T - 1) / T;
    const int gP   = (NE * 16 + T - 1) / T;        // prop grid (16 lanes/edge)

    // ---- degree & norm ----
    zero_kernel<<<gN, T>>>(pDeg, NN);
    deg_kernel<<<gE, T>>>(dst);
    dis_kernel<<<gN, T>>>();
    norm_kernel<<<gE, T>>>(src, dst);

    // ---- LightGCN propagation: out = sum_l alpha * x^(l) ----
    init_out_zero_kernel<<<gND, T>>>(emb, pA);         // out = alpha*emb; A = 0

    prop_kernel<<<gP, T>>>(emb, pA, src, dst);         // layer 1: emb -> A
    accum_zero_kernel<<<gND, T>>>(pA, pB);             // out += alpha*A; B = 0

    prop_kernel<<<gP, T>>>(pA, pB, src, dst);          // layer 2: A -> B
    accum_zero_kernel<<<gND, T>>>(pB, pA);             // out += alpha*B; A = 0

    prop_kernel<<<gP, T>>>(pB, pA, src, dst);          // layer 3: B -> A
    accum_kernel<<<gND, T>>>(pA);                      // out += alpha*A

    // ---- scorer MLP ----
    mlp_kernel<<<NL, DIM>>>(lsrc, ldst, W1, b1, W2, b2);

    // ---- outputs: pred first, then loss in the trailing slot (if present) ----
    int npred = out_size < NL ? out_size : NL;
    if (npred > 0)
        pred_copy_kernel<<<(npred + T - 1) / T, T>>>(out, npred);
    if (out_size != NL) {
        float* lossp = out + (out_size - 1);
        zero_one_kernel<<<1, 32>>>(lossp);
        loss_kernel<<<132, 256>>>(elab, lossp);
    }
}

// round 3
// speedup vs baseline: 3.0124x; 1.7130x over previous
#include <cuda_runtime.h>

#define NN 100000          // nodes
#define DIM 64             // embed dim
#define NE 1600000         // edges
#define NL 100000          // label edges
#define ALPHA 0.25f        // 1/(NLAYERS+1), NLAYERS=3
#define SCAN_B 1024
#define NB ((NN + SCAN_B - 1) / SCAN_B)   // 98 scan blocks

// ---------------- scratch (device globals; no allocation allowed) -------------
__device__ int   g_cnt[NN];            // int degree / fill counters
__device__ float g_dinv[NN];           // deg^-1/2
__device__ int   g_rowptr[NN + 1];     // CSR row pointers (by dst)
__device__ int   g_bsum[NB];           // scan block sums
__device__ int   g_csr_src[NE];        // CSR column indices (src nodes)
__device__ float g_A[NN * DIM];        // ping (pre-scaled y)
__device__ float g_B[NN * DIM];        // pong
__device__ float g_out[NN * DIM];      // LightGCN accumulated embedding
__device__ float g_pred[NL];           // MLP predictions

// ---------------- degree / dinv ----------------------------------------------
__global__ void zero_cnt_kernel() {
    int i = blockIdx.x * blockDim.x + threadIdx.x;
    if (i < NN) g_cnt[i] = 0;
}

__global__ void deg_kernel(const int* __restrict__ dst) {
    int e = blockIdx.x * blockDim.x + threadIdx.x;
    if (e < NE) atomicAdd(&g_cnt[dst[e]], 1);
}

__global__ void dinv_kernel() {
    int i = blockIdx.x * blockDim.x + threadIdx.x;
    if (i < NN) {
        int d = g_cnt[i];
        g_dinv[i] = (d > 0) ? rsqrtf((float)d) : 0.0f;
    }
}

// ---------------- CSR build: prefix sum + fill --------------------------------
__global__ void scan_block_kernel() {
    __shared__ int sh[SCAN_B];
    int i = blockIdx.x * SCAN_B + threadIdx.x;
    int v = (i < NN) ? g_cnt[i] : 0;
    sh[threadIdx.x] = v;
    __syncthreads();
#pragma unroll
    for (int off = 1; off < SCAN_B; off <<= 1) {
        int t = 0;
        if (threadIdx.x >= off) t = sh[threadIdx.x - off];
        __syncthreads();
        if (threadIdx.x >= off) sh[threadIdx.x] += t;
        __syncthreads();
    }
    if (i < NN) g_rowptr[i] = sh[threadIdx.x] - v;   // exclusive within block
    if (threadIdx.x == SCAN_B - 1) g_bsum[blockIdx.x] = sh[SCAN_B - 1];
}

__global__ void scan_bsum_kernel() {
    if (threadIdx.x == 0 && blockIdx.x == 0) {
        int acc = 0;
        for (int i = 0; i < NB; i++) { int v = g_bsum[i]; g_bsum[i] = acc; acc += v; }
    }
}

__global__ void add_offset_kernel() {
    int i = blockIdx.x * blockDim.x + threadIdx.x;
    if (i < NN) g_rowptr[i] += g_bsum[i >> 10];
    if (i == 0) g_rowptr[NN] = NE;
}

__global__ void fill_csr_kernel(const int* __restrict__ src, const int* __restrict__ dst) {
    int e = blockIdx.x * blockDim.x + threadIdx.x;
    if (e < NE) {
        int d = dst[e];
        int pos = atomicAdd(&g_cnt[d], 1);
        g_csr_src[g_rowptr[d] + pos] = src[e];
    }
}

// ---------------- init: out = alpha*emb; y0 = dinv * emb ----------------------
__global__ void init_kernel(const float* __restrict__ emb, float* __restrict__ y) {
    int i = blockIdx.x * blockDim.x + threadIdx.x;   // float4 index
    if (i >= NN * (DIM / 4)) return;
    int n = i >> 4;
    float di = __ldg(g_dinv + n);
    float4 v = reinterpret_cast<const float4*>(emb)[i];
    float4 o = {v.x * ALPHA, v.y * ALPHA, v.z * ALPHA, v.w * ALPHA};
    reinterpret_cast<float4*>(g_out)[i] = o;
    float4 s = {v.x * di, v.y * di, v.z * di, v.w * di};
    reinterpret_cast<float4*>(y)[i] = s;
}

// ---------------- gather layer ------------------------------------------------
// 16 lanes per node; lane owns one float4 column chunk.
// acc = sum over in-edges of y[src];  x = acc*dinv[n];
// out += alpha*x;  y_next = x*dinv[n] (pre-scaled for next layer)
__global__ void __launch_bounds__(256) gather_kernel(const float* __restrict__ y,
                                                     float* __restrict__ ynext,
                                                     int write_next) {
    int idx = blockIdx.x * blockDim.x + threadIdx.x;
    int n = idx >> 4;
    if (n >= NN) return;
    int lane = idx & 15;

    int beg = __ldg(g_rowptr + n);
    int end = __ldg(g_rowptr + n + 1);

    float4 acc = {0.0f, 0.0f, 0.0f, 0.0f};
    for (int e = beg; e < end; e++) {
        int s = __ldg(g_csr_src + e);
        const float4 v = *reinterpret_cast<const float4*>(y + ((long long)s << 6) + (lane << 2));
        acc.x += v.x; acc.y += v.y; acc.z += v.z; acc.w += v.w;
    }
    float di = __ldg(g_dinv + n);
    // x = acc * di
    float4 x = {acc.x * di, acc.y * di, acc.z * di, acc.w * di};

    long long off = ((long long)n << 6) + (lane << 2);
    float4* po = reinterpret_cast<float4*>(g_out + off);
    float4 o = *po;
    o.x += x.x * ALPHA; o.y += x.y * ALPHA; o.z += x.z * ALPHA; o.w += x.w * ALPHA;
    *po = o;

    if (write_next) {
        float4 yn = {x.x * di, x.y * di, x.z * di, x.w * di};
        *reinterpret_cast<float4*>(ynext + off) = yn;
    }
}

// ---------------- MLP scorer: one block (64 threads) per label edge ----------
__global__ void mlp_kernel(const int* __restrict__ lsrc,
                           const int* __restrict__ ldst,
                           const float* __restrict__ W1,   // [128,64] row-major
                           const float* __restrict__ b1,   // [64]
                           const float* __restrict__ W2,   // [64]
                           const float* __restrict__ b2) { // [1]
    __shared__ float sh_in[2 * DIM];
    __shared__ float sh_h[DIM];
    int l = blockIdx.x;
    int t = threadIdx.x;   // 0..63

    int s = __ldg(lsrc + l);
    int d = __ldg(ldst + l);
    sh_in[t]       = g_out[(long long)s * DIM + t];
    sh_in[DIM + t] = g_out[(long long)d * DIM + t];
    __syncthreads();

    float acc = __ldg(b1 + t);
#pragma unroll 8
    for (int i = 0; i < 2 * DIM; i++)
        acc = fmaf(sh_in[i], __ldg(W1 + i * DIM + t), acc);
    acc = fmaxf(acc, 0.0f);
    sh_h[t] = acc * __ldg(W2 + t);
    __syncthreads();

    if (t < 32) {
        float v = sh_h[t] + sh_h[t + 32];
#pragma unroll
        for (int off = 16; off > 0; off >>= 1)
            v += __shfl_down_sync(0xffffffffu, v, off);
        if (t == 0) g_pred[l] = v + __ldg(b2);
    }
}

// ---------------- output: pred copy + MSE loss -------------------------------
__global__ void pred_copy_kernel(float* __restrict__ out, int n) {
    int i = blockIdx.x * blockDim.x + threadIdx.x;
    if (i < n) out[i] = g_pred[i];
}

__global__ void zero_one_kernel(float* p) {
    if (threadIdx.x == 0 && blockIdx.x == 0) *p = 0.0f;
}

__global__ void loss_kernel(const float* __restrict__ label, float* __restrict__ out_loss) {
    __shared__ float sh[256];
    float acc = 0.0f;
    for (int i = blockIdx.x * blockDim.x + threadIdx.x; i < NL; i += gridDim.x * blockDim.x) {
        float diff = g_pred[i] - label[i];
        acc += diff * diff;
    }
    sh[threadIdx.x] = acc;
    __syncthreads();
    for (int stride = 128; stride > 0; stride >>= 1) {
        if (threadIdx.x < stride) sh[threadIdx.x] += sh[threadIdx.x + stride];
        __syncthreads();
    }
    if (threadIdx.x == 0) atomicAdd(out_loss, sh[0] * (1.0f / NL));
}

// ---------------- host launcher ----------------------------------------------
extern "C" void kernel_launch(void* const* d_in, const int* in_sizes, int n_in,
                              void* d_out, int out_size) {
    const int*   ei   = (const int*)d_in[0];       // [2, NE]
    const int*   eli  = (const int*)d_in[1];       // [2, NL]
    const float* elab = (const float*)d_in[2];     // [NL]
    const float* emb  = (const float*)d_in[3];     // [NN, 64]
    const float* W1   = (const float*)d_in[4];     // [128, 64]
    const float* b1   = (const float*)d_in[5];     // [64]
    const float* W2   = (const float*)d_in[6];     // [64, 1]
    const float* b2   = (const float*)d_in[7];     // [1]
    float* out = (float*)d_out;

    const int* src = ei;
    const int* dst = ei + NE;
    const int* lsrc = eli;
    const int* ldst = eli + NL;

    float *pA, *pB;
    cudaGetSymbolAddress((void**)&pA, g_A);
    cudaGetSymbolAddress((void**)&pB, g_B);

    const int T = 256;
    const int gE  = (NE + T - 1) / T;
    const int gN  = (NN + T - 1) / T;
    const int gI  = (NN * (DIM / 4) + T - 1) / T;  // init (float4 granularity)
    const int gG  = (NN * 16 + T - 1) / T;         // gather (16 lanes/node)

    // ---- degree & dinv ----
    zero_cnt_kernel<<<gN, T>>>();
    deg_kernel<<<gE, T>>>(dst);
    dinv_kernel<<<gN, T>>>();

    // ---- CSR build (by dst) ----
    scan_block_kernel<<<NB, SCAN_B>>>();
    scan_bsum_kernel<<<1, 32>>>();
    add_offset_kernel<<<gN, T>>>();
    zero_cnt_kernel<<<gN, T>>>();
    fill_csr_kernel<<<gE, T>>>(src, dst);

    // ---- LightGCN: out = alpha * sum_l x^(l), pull-style gather layers ----
    init_kernel<<<gI, T>>>(emb, pA);               // out=alpha*emb; A = dinv*emb
    gather_kernel<<<gG, T>>>(pA, pB, 1);           // layer 1: A -> B (pre-scaled)
    gather_kernel<<<gG, T>>>(pB, pA, 1);           // layer 2: B -> A
    gather_kernel<<<gG, T>>>(pA, pB, 0);           // layer 3: out += only

    // ---- scorer MLP ----
    mlp_kernel<<<NL, DIM>>>(lsrc, ldst, W1, b1, W2, b2);

    // ---- outputs: pred first, then loss in the trailing slot (if present) ----
    int npred = out_size < NL ? out_size : NL;
    if (npred > 0)
        pred_copy_kernel<<<(npred + T - 1) / T, T>>>(out, npred);
    if (out_size != NL) {
        float* lossp = out + (out_size - 1);
        zero_one_kernel<<<1, 32>>>(lossp);
        loss_kernel<<<132, 256>>>(elab, lossp);
    }
}

// round 5
// speedup vs baseline: 4.1053x; 1.3628x over previous
#include <cuda_runtime.h>

#define NN 100000          // nodes
#define DIM 64             // embed dim
#define NE 1600000         // edges
#define NL 100000          // label edges
#define ALPHA 0.25f        // 1/(NLAYERS+1), NLAYERS=3
#define SCAN_B 1024
#define NB ((NN + SCAN_B - 1) / SCAN_B)   // 98 scan blocks

#define TILE_E 32          // edges per MLP tile
#define INROW 132          // padded sIn row (floats) — avoids 512B-stride conflicts
#define MLP_BLOCKS 592     // 4 per SM (148 SMs)
#define N_TILES (NL / TILE_E)   // 3125 exact

// dynamic smem layout (floats): W1[8192] | sIn[TILE_E*INROW] | b1[64] | W2[64] | sS[32 int] | sD[32 int]
#define SM_W1   0
#define SM_IN   (8192)
#define SM_B1   (SM_IN + TILE_E * INROW)
#define SM_W2   (SM_B1 + 64)
#define SM_S    (SM_W2 + 64)
#define SM_D    (SM_S + 32)
#define SM_TOT  (SM_D + 32)                 // 12608 floats = 50432 bytes

// ---------------- scratch (device globals; no allocation allowed) -------------
__device__ int   g_cnt[NN];            // int degree / fill counters
__device__ float g_dinv[NN];           // deg^-1/2
__device__ int   g_rowptr[NN + 1];     // CSR row pointers (by dst)
__device__ int   g_bsum[NB];           // scan block sums
__device__ int   g_csr_src[NE];        // CSR column indices (src nodes)
__device__ float g_A[NN * DIM];        // ping (pre-scaled y)
__device__ float g_B[NN * DIM];        // pong
__device__ float g_out[NN * DIM];      // LightGCN accumulated embedding
__device__ float g_pred[NL];           // MLP predictions

// ---------------- degree / dinv ----------------------------------------------
__global__ void zero_cnt_kernel() {
    int i = blockIdx.x * blockDim.x + threadIdx.x;
    if (i < NN) g_cnt[i] = 0;
}

__global__ void deg_kernel(const int* __restrict__ dst) {
    int e = blockIdx.x * blockDim.x + threadIdx.x;
    if (e < NE) atomicAdd(&g_cnt[dst[e]], 1);
}

__global__ void dinv_kernel() {
    int i = blockIdx.x * blockDim.x + threadIdx.x;
    if (i < NN) {
        int d = g_cnt[i];
        g_dinv[i] = (d > 0) ? rsqrtf((float)d) : 0.0f;
    }
}

// ---------------- CSR build: prefix sum + fill --------------------------------
__global__ void scan_block_kernel() {
    __shared__ int sh[SCAN_B];
    int i = blockIdx.x * SCAN_B + threadIdx.x;
    int v = (i < NN) ? g_cnt[i] : 0;
    sh[threadIdx.x] = v;
    __syncthreads();
#pragma unroll
    for (int off = 1; off < SCAN_B; off <<= 1) {
        int t = 0;
        if (threadIdx.x >= off) t = sh[threadIdx.x - off];
        __syncthreads();
        if (threadIdx.x >= off) sh[threadIdx.x] += t;
        __syncthreads();
    }
    if (i < NN) g_rowptr[i] = sh[threadIdx.x] - v;   // exclusive within block
    if (threadIdx.x == SCAN_B - 1) g_bsum[blockIdx.x] = sh[SCAN_B - 1];
}

__global__ void scan_bsum_kernel() {
    if (threadIdx.x == 0 && blockIdx.x == 0) {
        int acc = 0;
        for (int i = 0; i < NB; i++) { int v = g_bsum[i]; g_bsum[i] = acc; acc += v; }
    }
}

__global__ void add_offset_kernel() {
    int i = blockIdx.x * blockDim.x + threadIdx.x;
    if (i < NN) g_rowptr[i] += g_bsum[i >> 10];
    if (i == 0) g_rowptr[NN] = NE;
}

__global__ void fill_csr_kernel(const int* __restrict__ src, const int* __restrict__ dst) {
    int e = blockIdx.x * blockDim.x + threadIdx.x;
    if (e < NE) {
        int d = dst[e];
        int pos = atomicAdd(&g_cnt[d], 1);
        g_csr_src[g_rowptr[d] + pos] = src[e];
    }
}

// ---------------- init: out = alpha*emb; y0 = dinv * emb ----------------------
__global__ void init_kernel(const float* __restrict__ emb, float* __restrict__ y) {
    int i = blockIdx.x * blockDim.x + threadIdx.x;   // float4 index
    if (i >= NN * (DIM / 4)) return;
    int n = i >> 4;
    float di = __ldg(g_dinv + n);
    float4 v = reinterpret_cast<const float4*>(emb)[i];
    float4 o = {v.x * ALPHA, v.y * ALPHA, v.z * ALPHA, v.w * ALPHA};
    reinterpret_cast<float4*>(g_out)[i] = o;
    float4 s = {v.x * di, v.y * di, v.z * di, v.w * di};
    reinterpret_cast<float4*>(y)[i] = s;
}

// ---------------- gather layer ------------------------------------------------
// 16 lanes per node; lane owns one float4 column chunk. Edge loop unrolled x4.
__global__ void __launch_bounds__(256) gather_kernel(const float* __restrict__ y,
                                                     float* __restrict__ ynext,
                                                     int write_next) {
    int idx = blockIdx.x * blockDim.x + threadIdx.x;
    int n = idx >> 4;
    if (n >= NN) return;
    int lane4 = (idx & 15) << 2;   // float offset within row

    int beg = __ldg(g_rowptr + n);
    int end = __ldg(g_rowptr + n + 1);

    float4 acc = {0.0f, 0.0f, 0.0f, 0.0f};
    int e = beg;
    for (; e + 4 <= end; e += 4) {
        int s0 = __ldg(g_csr_src + e + 0);
        int s1 = __ldg(g_csr_src + e + 1);
        int s2 = __ldg(g_csr_src + e + 2);
        int s3 = __ldg(g_csr_src + e + 3);
        float4 v0 = *reinterpret_cast<const float4*>(y + ((long long)s0 << 6) + lane4);
        float4 v1 = *reinterpret_cast<const float4*>(y + ((long long)s1 << 6) + lane4);
        float4 v2 = *reinterpret_cast<const float4*>(y + ((long long)s2 << 6) + lane4);
        float4 v3 = *reinterpret_cast<const float4*>(y + ((long long)s3 << 6) + lane4);
        acc.x += (v0.x + v1.x) + (v2.x + v3.x);
        acc.y += (v0.y + v1.y) + (v2.y + v3.y);
        acc.z += (v0.z + v1.z) + (v2.z + v3.z);
        acc.w += (v0.w + v1.w) + (v2.w + v3.w);
    }
    for (; e < end; e++) {
        int s = __ldg(g_csr_src + e);
        const float4 v = *reinterpret_cast<const float4*>(y + ((long long)s << 6) + lane4);
        acc.x += v.x; acc.y += v.y; acc.z += v.z; acc.w += v.w;
    }
    float di = __ldg(g_dinv + n);
    float4 x = {acc.x * di, acc.y * di, acc.z * di, acc.w * di};

    long long off = ((long long)n << 6) + lane4;
    float4* po = reinterpret_cast<float4*>(g_out + off);
    float4 o = *po;
    o.x += x.x * ALPHA; o.y += x.y * ALPHA; o.z += x.z * ALPHA; o.w += x.w * ALPHA;
    *po = o;

    if (write_next) {
        float4 yn = {x.x * di, x.y * di, x.z * di, x.w * di};
        *reinterpret_cast<float4*>(ynext + off) = yn;
    }
}

// ---------------- MLP scorer: persistent register-tiled GEMM ------------------
// Dynamic smem: W1 [128x64] + b1 + W2 cached once per block, sIn per tile.
// Per tile of 32 edges: gather [32][128] inputs (padded rows), each thread
// computes a 4-hidden x 2-edge register tile, then fused ReLU + W2 dot +
// width-16 shuffle reduction. Writes pred to g_pred and d_out directly.
__global__ void __launch_bounds__(256) mlp_kernel(const int* __restrict__ lsrc,
                           const int* __restrict__ ldst,
                           const float* __restrict__ W1,   // [128,64] row-major
                           const float* __restrict__ b1,   // [64]
                           const float* __restrict__ W2,   // [64]
                           const float* __restrict__ b2,   // [1]
                           float* __restrict__ out, int npred) {
    extern __shared__ float sm[];
    float* sW1 = sm + SM_W1;
    float* sIn = sm + SM_IN;
    float* sB1 = sm + SM_B1;
    float* sW2 = sm + SM_W2;
    int*   sS  = (int*)(sm + SM_S);
    int*   sD  = (int*)(sm + SM_D);

    int t = threadIdx.x;

    // cache weights once per block
    for (int k = t; k < 128 * 16; k += 256)       // float4 granularity: 2048 float4s
        reinterpret_cast<float4*>(sW1)[k] = reinterpret_cast<const float4*>(W1)[k];
    if (t < 64) { sB1[t] = b1[t]; sW2[t] = W2[t]; }
    float bias2 = __ldg(b2);

    // compute-tile mapping: thread t -> hidden quad h4, edge group eg (2 edges)
    int h4 = (t & 15) << 2;        // 0,4,...,60
    int eg = t >> 4;               // 0..15
    int e0 = eg * 2, e1 = eg * 2 + 1;

    for (int tile = blockIdx.x; tile < N_TILES; tile += gridDim.x) {
        int base = tile * TILE_E;
        __syncthreads();           // protect sIn/sS/sD reuse from previous tile
        if (t < TILE_E) {
            sS[t] = __ldg(lsrc + base + t);
            sD[t] = __ldg(ldst + base + t);
        }
        __syncthreads();

        // gather inputs: thread t -> edge e=t>>3, float4 slots q, q+8, q+16, q+24
        {
            int e = t >> 3, q = t & 7;
            int s = sS[e], d = sD[e];
            const float4* rs = reinterpret_cast<const float4*>(g_out + ((long long)s << 6));
            const float4* rd = reinterpret_cast<const float4*>(g_out + ((long long)d << 6));
            float* row = sIn + e * INROW;
#pragma unroll
            for (int jj = 0; jj < 4; jj++) {
                int j = q + jj * 8;
                float4 v = (j < 16) ? rs[j] : rd[j - 16];
                *reinterpret_cast<float4*>(row + j * 4) = v;
            }
        }
        __syncthreads();

        // register-tiled GEMM: acc[edge][hidden]
        float a00 = 0.f, a01 = 0.f, a02 = 0.f, a03 = 0.f;
        float a10 = 0.f, a11 = 0.f, a12 = 0.f, a13 = 0.f;
        const float* r0 = sIn + e0 * INROW;
        const float* r1 = sIn + e1 * INROW;
#pragma unroll 8
        for (int i = 0; i < 128; i++) {
            float4 w = *reinterpret_cast<const float4*>(sW1 + i * 64 + h4);
            float x0 = r0[i];
            float x1 = r1[i];
            a00 = fmaf(x0, w.x, a00); a01 = fmaf(x0, w.y, a01);
            a02 = fmaf(x0, w.z, a02); a03 = fmaf(x0, w.w, a03);
            a10 = fmaf(x1, w.x, a10); a11 = fmaf(x1, w.y, a11);
            a12 = fmaf(x1, w.z, a12); a13 = fmaf(x1, w.w, a13);
        }

        // ReLU + W2 dot (4 hidden units per thread)
        float p0, p1;
        {
            float bb0 = sB1[h4], bb1 = sB1[h4 + 1], bb2v = sB1[h4 + 2], bb3 = sB1[h4 + 3];
            float w0 = sW2[h4], w1 = sW2[h4 + 1], w2v = sW2[h4 + 2], w3 = sW2[h4 + 3];
            p0 = fmaxf(a00 + bb0, 0.f) * w0 + fmaxf(a01 + bb1, 0.f) * w1
               + fmaxf(a02 + bb2v, 0.f) * w2v + fmaxf(a03 + bb3, 0.f) * w3;
            p1 = fmaxf(a10 + bb0, 0.f) * w0 + fmaxf(a11 + bb1, 0.f) * w1
               + fmaxf(a12 + bb2v, 0.f) * w2v + fmaxf(a13 + bb3, 0.f) * w3;
        }

        // reduce across the 16 hidden-quad lanes (width-16 shuffles)
#pragma unroll
        for (int off = 8; off > 0; off >>= 1) {
            p0 += __shfl_down_sync(0xffffffffu, p0, off, 16);
            p1 += __shfl_down_sync(0xffffffffu, p1, off, 16);
        }
        if ((t & 15) == 0) {
            float v0 = p0 + bias2;
            float v1 = p1 + bias2;
            g_pred[base + e0] = v0;
            g_pred[base + e1] = v1;
            if (base + e0 < npred) out[base + e0] = v0;
            if (base + e1 < npred) out[base + e1] = v1;
        }
    }
}

// ---------------- loss ---------------------------------------------------------
__global__ void zero_one_kernel(float* p) {
    if (threadIdx.x == 0 && blockIdx.x == 0) *p = 0.0f;
}

__global__ void loss_kernel(const float* __restrict__ label, float* __restrict__ out_loss) {
    __shared__ float sh[256];
    float acc = 0.0f;
    for (int i = blockIdx.x * blockDim.x + threadIdx.x; i < NL; i += gridDim.x * blockDim.x) {
        float diff = g_pred[i] - label[i];
        acc += diff * diff;
    }
    sh[threadIdx.x] = acc;
    __syncthreads();
    for (int stride = 128; stride > 0; stride >>= 1) {
        if (threadIdx.x < stride) sh[threadIdx.x] += sh[threadIdx.x + stride];
        __syncthreads();
    }
    if (threadIdx.x == 0) atomicAdd(out_loss, sh[0] * (1.0f / NL));
}

// ---------------- host launcher ----------------------------------------------
extern "C" void kernel_launch(void* const* d_in, const int* in_sizes, int n_in,
                              void* d_out, int out_size) {
    const int*   ei   = (const int*)d_in[0];       // [2, NE]
    const int*   eli  = (const int*)d_in[1];       // [2, NL]
    const float* elab = (const float*)d_in[2];     // [NL]
    const float* emb  = (const float*)d_in[3];     // [NN, 64]
    const float* W1   = (const float*)d_in[4];     // [128, 64]
    const float* b1   = (const float*)d_in[5];     // [64]
    const float* W2   = (const float*)d_in[6];     // [64, 1]
    const float* b2   = (const float*)d_in[7];     // [1]
    float* out = (float*)d_out;

    const int* src = ei;
    const int* dst = ei + NE;
    const int* lsrc = eli;
    const int* ldst = eli + NL;

    float *pA, *pB;
    cudaGetSymbolAddress((void**)&pA, g_A);
    cudaGetSymbolAddress((void**)&pB, g_B);

    const int T = 256;
    const int gE  = (NE + T - 1) / T;
    const int gN  = (NN + T - 1) / T;
    const int gI  = (NN * (DIM / 4) + T - 1) / T;  // init (float4 granularity)
    const int gG  = (NN * 16 + T - 1) / T;         // gather (16 lanes/node)
    const int smemBytes = SM_TOT * 4;              // ~50.4 KB dynamic

    static int s_attr_done = 0;
    if (!s_attr_done) {
        cudaFuncSetAttribute(mlp_kernel, cudaFuncAttributeMaxDynamicSharedMemorySize, smemBytes);
        s_attr_done = 1;
    }

    // ---- degree & dinv ----
    zero_cnt_kernel<<<gN, T>>>();
    deg_kernel<<<gE, T>>>(dst);
    dinv_kernel<<<gN, T>>>();

    // ---- CSR build (by dst) ----
    scan_block_kernel<<<NB, SCAN_B>>>();
    scan_bsum_kernel<<<1, 32>>>();
    add_offset_kernel<<<gN, T>>>();
    zero_cnt_kernel<<<gN, T>>>();
    fill_csr_kernel<<<gE, T>>>(src, dst);

    // ---- LightGCN: out = alpha * sum_l x^(l), pull-style gather layers ----
    init_kernel<<<gI, T>>>(emb, pA);               // out=alpha*emb; A = dinv*emb
    gather_kernel<<<gG, T>>>(pA, pB, 1);           // layer 1: A -> B (pre-scaled)
    gather_kernel<<<gG, T>>>(pB, pA, 1);           // layer 2: B -> A
    gather_kernel<<<gG, T>>>(pA, pB, 0);           // layer 3: out += only

    // ---- scorer MLP (writes g_pred and d_out directly) ----
    int npred = out_size < NL ? out_size : NL;
    mlp_kernel<<<MLP_BLOCKS, 256, smemBytes>>>(lsrc, ldst, W1, b1, W2, b2, out, npred);

    // ---- loss in the trailing slot (if present) ----
    if (out_size != NL) {
        float* lossp = out + (out_size - 1);
        zero_one_kernel<<<1, 32>>>(lossp);
        loss_kernel<<<132, 256>>>(elab, lossp);
    }
}